// round 1
// baseline (speedup 1.0000x reference)
#include <cuda_runtime.h>

#define HH 512
#define WW 512
#define HW (512*512)
#define NB 16

// Scratch (static device memory — no runtime allocation)
__device__ float g_tmp[32 * HW];   // row-max intermediate (16 src + 16 ref planes)
__device__ float g_mse[NB * HW];   // expanded eye mask (source)
__device__ float g_mre[NB * HW];   // expanded eye mask (ref)
__device__ int   g_hist[NB * 24 * 256];  // [b][match(4)][side(2)][ch(3)][bin]
__device__ int   g_table[NB * 12 * 256]; // [b][match(4)][ch(3)][bin]

__device__ __forceinline__ float denorm255(float x) {
    return fminf(fmaxf((x + 1.0f) * 0.5f, 0.0f), 1.0f) * 255.0f;
}

__global__ void k_zero() {
    int i = blockIdx.x * 1024 + threadIdx.x;
    if (i < NB * 24 * 256) g_hist[i] = 0;
}

// Horizontal 25-wide max of (mask[2] + mask[3]); plane<16 => source masks
__global__ void k_rowmax(const float* __restrict__ ms, const float* __restrict__ mr) {
    int plane = blockIdx.z;
    int b = plane & 15;
    const float* mk = ((plane < 16) ? ms : mr) + (size_t)b * 5 * HW;
    const float* p2 = mk + 2 * HW;
    const float* p3 = mk + 3 * HW;
    int y = blockIdx.y;
    int x0 = blockIdx.x * 256;
    __shared__ float srow[280];
    for (int i = threadIdx.x; i < 280; i += 256) {
        int x = x0 - 12 + i;
        float v = 0.0f;
        if (x >= 0 && x < WW) v = p2[y * WW + x] + p3[y * WW + x];
        srow[i] = v;
    }
    __syncthreads();
    float mx = 0.0f;
#pragma unroll
    for (int j = 0; j < 25; j++) mx = fmaxf(mx, srow[threadIdx.x + j]);
    g_tmp[(size_t)plane * HW + y * WW + x0 + threadIdx.x] = mx;
}

// Vertical 25-tall max of g_tmp, multiplied by mask[1] -> g_mse / g_mre
__global__ void k_colmax(const float* __restrict__ ms, const float* __restrict__ mr) {
    int plane = blockIdx.z;
    int b = plane & 15;
    const float* m1 = ((plane < 16) ? ms : mr) + (size_t)b * 5 * HW + HW;
    int x0 = blockIdx.x * 32, y0 = blockIdx.y * 8;
    __shared__ float t[32][33];
    int tid = threadIdx.y * 32 + threadIdx.x;
    for (int j = tid; j < 1024; j += 256) {
        int ry = j >> 5, cx = j & 31;
        int y = y0 - 12 + ry;
        float v = 0.0f;
        if (y >= 0 && y < HH) v = g_tmp[(size_t)plane * HW + y * WW + x0 + cx];
        t[ry][cx] = v;
    }
    __syncthreads();
    float mx = 0.0f;
#pragma unroll
    for (int j = 0; j < 25; j++) mx = fmaxf(mx, t[threadIdx.y + j][threadIdx.x]);
    int pix = (y0 + threadIdx.y) * WW + x0 + threadIdx.x;
    float out = mx * m1[pix];
    if (plane < 16) g_mse[b * HW + pix] = out;
    else            g_mre[b * HW + pix] = out;
}

// Weighted histograms (integer weights; exact). 24 hists per batch in shared.
__global__ void k_hist(const float* __restrict__ src, const float* __restrict__ tgt,
                       const float* __restrict__ ms, const float* __restrict__ mr) {
    __shared__ int sh[6144];
    int tid = threadIdx.x;
    for (int j = tid; j < 6144; j += 512) sh[j] = 0;
    __syncthreads();
    int b = blockIdx.y;
    const float* is  = src + (size_t)b * 3 * HW;
    const float* ir  = tgt + (size_t)b * 3 * HW;
    const float* mss = ms  + (size_t)b * 5 * HW;
    const float* mrr = mr  + (size_t)b * 5 * HW;
    const float* mseb = g_mse + b * HW;
    const float* mreb = g_mre + b * HW;
    for (int i = blockIdx.x * 512 + tid; i < HW; i += 32 * 512) {
        float ws[4] = { mss[HW + i], mss[4 * HW + i], mss[i], mseb[i] };
        float wr[4] = { mrr[HW + i], mrr[4 * HW + i], mrr[i], mreb[i] };
#pragma unroll
        for (int c = 0; c < 3; c++) {
            float dsv = denorm255(is[c * HW + i]);
            float drv = denorm255(ir[c * HW + i]);
#pragma unroll
            for (int m = 0; m < 4; m++) {
                if (ws[m] > 0.0f) {
                    int bin = min((int)(dsv * ws[m]), 255);
                    atomicAdd(&sh[((m * 2 + 0) * 3 + c) * 256 + bin], (int)ws[m]);
                }
                if (wr[m] > 0.0f) {
                    int bin = min((int)(drv * wr[m]), 255);
                    atomicAdd(&sh[((m * 2 + 1) * 3 + c) * 256 + bin], (int)wr[m]);
                }
            }
        }
    }
    __syncthreads();
    int* gh = g_hist + b * 6144;
    for (int j = tid; j < 6144; j += 512)
        if (sh[j]) atomicAdd(&gh[j], sh[j]);
}

// Per (batch, match, channel): cumsum -> cdf -> searchsorted (side=left) -> table
__global__ void k_table() {
    int b = blockIdx.y;
    int match = blockIdx.x / 3, c = blockIdx.x % 3;
    int i = threadIdx.x;
    const int* hb = g_hist + b * 6144;
    int hs = hb[((match * 2 + 0) * 3 + c) * 256 + i];
    int hr = hb[((match * 2 + 1) * 3 + c) * 256 + i];
    __shared__ int scS[256], scR[256];
    scS[i] = hs; scR[i] = hr;
    __syncthreads();
    for (int off = 1; off < 256; off <<= 1) {
        int vs = (i >= off) ? scS[i - off] : 0;
        int vr = (i >= off) ? scR[i - off] : 0;
        __syncthreads();
        scS[i] += vs; scR[i] += vr;
        __syncthreads();
    }
    float totS = (float)scS[255];
    float totR = (float)scR[255];
    float cs = (float)scS[i] / fmaxf(totS, 1e-6f);
    __shared__ float cdfR[256];
    cdfR[i] = (float)scR[i] / fmaxf(totR, 1e-6f);
    __syncthreads();
    int lo = 0, hi = 256;
    while (lo < hi) {
        int mid = (lo + hi) >> 1;
        if (cdfR[mid] < cs) lo = mid + 1; else hi = mid;
    }
    g_table[((b * 4 + match) * 3 + c) * 256 + i] = min(lo, 255);
}

// Final fused compose: 4 table lookups + blur + blends, tables + mse tile in shared
__global__ void k_compose(const float* __restrict__ src, const float* __restrict__ tgt,
                          const float* __restrict__ ms, float* __restrict__ out) {
    const int b = blockIdx.z;
    const int x0 = blockIdx.x * 128, y0 = blockIdx.y * 16;
    __shared__ int   stab[3072];
    __shared__ float smse[20 * 132];
    const int tid = threadIdx.x;
    for (int j = tid; j < 3072; j += 256) stab[j] = g_table[b * 3072 + j];
    for (int j = tid; j < 20 * 132; j += 256) {
        int ry = j / 132, cx = j % 132;
        int y = y0 - 2 + ry, x = x0 - 2 + cx;
        float v = 0.0f;
        if (y >= 0 && y < HH && x >= 0 && x < WW) v = g_mse[b * HW + y * WW + x];
        smse[j] = v;
    }
    __syncthreads();
    const float* is = src + (size_t)b * 3 * HW;
    const float* ir = tgt + (size_t)b * 3 * HW;
    const float* mk = ms  + (size_t)b * 5 * HW;
    float* ob = out + (size_t)b * 3 * HW;
    for (int k = tid; k < 2048; k += 256) {
        int row = k >> 7, col = k & 127;
        int idx = (y0 + row) * WW + x0 + col;
        float m1 = mk[HW + idx], m4 = mk[4 * HW + idx], m0 = mk[idx];
        float mse = smse[(row + 2) * 132 + col + 2];
        float mb = 0.0f;
        if (mse > 0.0f) {
            float s = 0.0f;
#pragma unroll
            for (int dy = 0; dy < 5; dy++)
#pragma unroll
                for (int dx = 0; dx < 5; dx++)
                    s += smse[(row + dy) * 132 + col + dx];
            mb = (s / 25.0f) * mse;
        }
#pragma unroll
        for (int c = 0; c < 3; c++) {
            float a   = is[c * HW + idx];
            float rch = ir[c * HW + idx];
            float d   = denorm255(a);
            float pgt = a;
            if (m1 > 0.0f) {   // skin match (idx 1)
                int bin = min((int)(d * m1), 255);
                float xm = ((float)stab[(0 * 3 + c) * 256 + bin] / 255.0f) * 2.0f - 1.0f;
                pgt = (1.0f - m1) * pgt + m1 * xm;
            }
            if (m4 > 0.0f) {   // idx 4 match
                int bin = min((int)(d * m4), 255);
                float xm = ((float)stab[(1 * 3 + c) * 256 + bin] / 255.0f) * 2.0f - 1.0f;
                pgt = (1.0f - m4) * pgt + m4 * xm;
            }
            if (m0 > 0.0f) {   // lip match (idx 0)
                int bin = min((int)(d * m0), 255);
                float xm = ((float)stab[(2 * 3 + c) * 256 + bin] / 255.0f) * 2.0f - 1.0f;
                pgt = (1.0f - m0) * pgt + m0 * xm;
            }
            if (mse > 0.0f) {  // eye match, blended with blurred mask
                int bin = min((int)(d * mse), 255);
                float xm = ((float)stab[(3 * 3 + c) * 256 + bin] / 255.0f) * 2.0f - 1.0f;
                pgt = (1.0f - mb) * pgt + mb * xm;
            }
            pgt = (1.0f - 0.3f * m1)  * pgt + 0.3f * m1  * rch;
            pgt = (1.0f - 0.8f * mse) * pgt + 0.8f * mse * rch;
            pgt = (1.0f - 0.1f * m0)  * pgt + 0.1f * m0  * rch;
            ob[c * HW + idx] = pgt;
        }
    }
}

extern "C" void kernel_launch(void* const* d_in, const int* in_sizes, int n_in,
                              void* d_out, int out_size) {
    const float* src = (const float*)d_in[0];  // sources  (16,3,512,512)
    const float* tgt = (const float*)d_in[1];  // targets
    const float* ms  = (const float*)d_in[2];  // mask_srcs (16,5,512,512)
    const float* mr  = (const float*)d_in[3];  // mask_tars
    float* out = (float*)d_out;

    k_zero<<<96, 1024>>>();
    k_rowmax<<<dim3(2, 512, 32), 256>>>(ms, mr);
    k_colmax<<<dim3(16, 64, 32), dim3(32, 8)>>>(ms, mr);
    k_hist<<<dim3(32, 16), 512>>>(src, tgt, ms, mr);
    k_table<<<dim3(12, 16), 256>>>();
    k_compose<<<dim3(4, 32, 16), 256>>>(src, tgt, ms, out);
}

// round 2
// speedup vs baseline: 1.5045x; 1.5045x over previous
#include <cuda_runtime.h>

#define HH 512
#define WW 512
#define HW (512*512)
#define NB 16

// Scratch (static device memory)
__device__ unsigned char g_tmp8[32 * HW];   // row-max intermediate (values 0..2)
__device__ unsigned char g_mse8[NB * HW];   // expanded eye mask (source), 0..2
__device__ unsigned char g_mre8[NB * HW];   // expanded eye mask (ref), 0..2
__device__ int   g_hist[NB * 24 * 256];     // [b][match(4)][side(2)][ch(3)][bin]
__device__ float g_tabf[NB * 12 * 256];     // pre-converted to renorm space

__device__ __forceinline__ float denorm255(float x) {
    return fminf(fmaxf((x + 1.0f) * 0.5f, 0.0f), 1.0f) * 255.0f;
}
__device__ __forceinline__ float fcomp(const float4& v, int p) {
    return p == 0 ? v.x : (p == 1 ? v.y : (p == 2 ? v.z : v.w));
}

__global__ void k_zero() {
    int i = blockIdx.x * 1024 + threadIdx.x;
    if (i < NB * 24 * 256) g_hist[i] = 0;
}

// Horizontal 25-wide max of (mask[2]+mask[3]) -> uint8. One row per block (128 thr).
__global__ void k_rowmax(const float* __restrict__ ms, const float* __restrict__ mr) {
    int plane = blockIdx.z;
    int b = plane & 15;
    const float* base = ((plane < 16) ? ms : mr) + (size_t)b * 5 * HW;
    int y = blockIdx.y;
    const float4* p2 = (const float4*)(base + 2 * HW + y * WW);
    const float4* p3 = (const float4*)(base + 3 * HW + y * WW);
    __shared__ float srow[536];
    int tid = threadIdx.x;
    {
        float4 a = p2[tid], c = p3[tid];
        float4 v = make_float4(a.x + c.x, a.y + c.y, a.z + c.z, a.w + c.w);
        *(float4*)&srow[12 + tid * 4] = v;
    }
    if (tid < 12) { srow[tid] = 0.0f; srow[524 + tid] = 0.0f; }
    __syncthreads();
    unsigned char* out = g_tmp8 + (size_t)plane * HW + y * WW;
#pragma unroll
    for (int r = 0; r < 4; r++) {
        int x = tid + r * 128;
        float mx = 0.0f;
#pragma unroll
        for (int j = 0; j < 25; j++) mx = fmaxf(mx, srow[x + j]);
        out[x] = (unsigned char)mx;
    }
}

// Vertical 25-tall max of g_tmp8, gated by mask[1] -> g_mse8 / g_mre8
__global__ void k_colmax(const float* __restrict__ ms, const float* __restrict__ mr) {
    int plane = blockIdx.z;
    int b = plane & 15;
    const float* m1 = ((plane < 16) ? ms : mr) + (size_t)b * 5 * HW + HW;
    int x0 = blockIdx.x * 32, y0 = blockIdx.y * 8;
    __shared__ unsigned char t[32][32];
    int tid = threadIdx.y * 32 + threadIdx.x;
    {
        int ry = tid >> 3;
        int cx = (tid & 7) * 4;
        int y = y0 - 12 + ry;
        uchar4 v = make_uchar4(0, 0, 0, 0);
        if (y >= 0 && y < HH)
            v = *(const uchar4*)(g_tmp8 + (size_t)plane * HW + y * WW + x0 + cx);
        *(uchar4*)&t[ry][cx] = v;
    }
    __syncthreads();
    int mx = 0;
#pragma unroll
    for (int j = 0; j < 25; j++) mx = max(mx, (int)t[threadIdx.y + j][threadIdx.x]);
    int pix = (y0 + threadIdx.y) * WW + x0 + threadIdx.x;
    unsigned char o = (m1[pix] > 0.0f) ? (unsigned char)mx : 0;
    ((plane < 16) ? g_mse8 : g_mre8)[b * HW + pix] = o;
}

// Weighted histograms, float4-vectorized, binary-mask fast path.
__global__ void k_hist(const float* __restrict__ src, const float* __restrict__ tgt,
                       const float* __restrict__ ms, const float* __restrict__ mr) {
    __shared__ int sh[6144];
    int tid = threadIdx.x;
    for (int j = tid; j < 6144; j += 512) sh[j] = 0;
    __syncthreads();
    int b = blockIdx.y;
    const float4* is  = (const float4*)(src + (size_t)b * 3 * HW);
    const float4* ir  = (const float4*)(tgt + (size_t)b * 3 * HW);
    const float4* mss = (const float4*)(ms  + (size_t)b * 5 * HW);
    const float4* mrr = (const float4*)(mr  + (size_t)b * 5 * HW);
    const uchar4* mse4 = (const uchar4*)(g_mse8 + (size_t)b * HW);
    const uchar4* mre4 = (const uchar4*)(g_mre8 + (size_t)b * HW);
    const int Q = HW / 4;  // 65536

    for (int i = blockIdx.x * 512 + tid; i < Q; i += 32 * 512) {
        float4 m1s = mss[Q + i], m4s = mss[4 * Q + i], m0s = mss[i];
        float4 m1r = mrr[Q + i], m4r = mrr[4 * Q + i], m0r = mrr[i];
        uchar4 es = mse4[i], er = mre4[i];
        float4 s0 = is[i], s1 = is[Q + i], s2 = is[2 * Q + i];
        float4 r0 = ir[i], r1 = ir[Q + i], r2 = ir[2 * Q + i];
        unsigned char esv[4] = { es.x, es.y, es.z, es.w };
        unsigned char erv[4] = { er.x, er.y, er.z, er.w };
#pragma unroll
        for (int p = 0; p < 4; p++) {
            // ---- source side ----
            float d0 = denorm255(fcomp(s0, p));
            float d1 = denorm255(fcomp(s1, p));
            float d2 = denorm255(fcomp(s2, p));
            int b0 = (int)d0, b1 = (int)d1, b2 = (int)d2;
            if (fcomp(m1s, p) > 0.0f) {   // match 0 (skin)
                atomicAdd(&sh[0 * 768 + 0 * 256 + b0], 1);
                atomicAdd(&sh[0 * 768 + 1 * 256 + b1], 1);
                atomicAdd(&sh[0 * 768 + 2 * 256 + b2], 1);
            }
            if (fcomp(m4s, p) > 0.0f) {   // match 1 (idx 4)
                atomicAdd(&sh[2 * 768 + 0 * 256 + b0], 1);
                atomicAdd(&sh[2 * 768 + 1 * 256 + b1], 1);
                atomicAdd(&sh[2 * 768 + 2 * 256 + b2], 1);
            }
            if (fcomp(m0s, p) > 0.0f) {   // match 2 (lip)
                atomicAdd(&sh[4 * 768 + 0 * 256 + b0], 1);
                atomicAdd(&sh[4 * 768 + 1 * 256 + b1], 1);
                atomicAdd(&sh[4 * 768 + 2 * 256 + b2], 1);
            }
            int w = esv[p];               // match 3 (eye), w in {0,1,2}
            if (w == 1) {
                atomicAdd(&sh[6 * 768 + 0 * 256 + b0], 1);
                atomicAdd(&sh[6 * 768 + 1 * 256 + b1], 1);
                atomicAdd(&sh[6 * 768 + 2 * 256 + b2], 1);
            } else if (w == 2) {
                atomicAdd(&sh[6 * 768 + 0 * 256 + min((int)(d0 * 2.0f), 255)], 2);
                atomicAdd(&sh[6 * 768 + 1 * 256 + min((int)(d1 * 2.0f), 255)], 2);
                atomicAdd(&sh[6 * 768 + 2 * 256 + min((int)(d2 * 2.0f), 255)], 2);
            }
            // ---- ref side ----
            float e0 = denorm255(fcomp(r0, p));
            float e1 = denorm255(fcomp(r1, p));
            float e2 = denorm255(fcomp(r2, p));
            int c0 = (int)e0, c1 = (int)e1, c2 = (int)e2;
            if (fcomp(m1r, p) > 0.0f) {
                atomicAdd(&sh[1 * 768 + 0 * 256 + c0], 1);
                atomicAdd(&sh[1 * 768 + 1 * 256 + c1], 1);
                atomicAdd(&sh[1 * 768 + 2 * 256 + c2], 1);
            }
            if (fcomp(m4r, p) > 0.0f) {
                atomicAdd(&sh[3 * 768 + 0 * 256 + c0], 1);
                atomicAdd(&sh[3 * 768 + 1 * 256 + c1], 1);
                atomicAdd(&sh[3 * 768 + 2 * 256 + c2], 1);
            }
            if (fcomp(m0r, p) > 0.0f) {
                atomicAdd(&sh[5 * 768 + 0 * 256 + c0], 1);
                atomicAdd(&sh[5 * 768 + 1 * 256 + c1], 1);
                atomicAdd(&sh[5 * 768 + 2 * 256 + c2], 1);
            }
            int wr = erv[p];
            if (wr == 1) {
                atomicAdd(&sh[7 * 768 + 0 * 256 + c0], 1);
                atomicAdd(&sh[7 * 768 + 1 * 256 + c1], 1);
                atomicAdd(&sh[7 * 768 + 2 * 256 + c2], 1);
            } else if (wr == 2) {
                atomicAdd(&sh[7 * 768 + 0 * 256 + min((int)(e0 * 2.0f), 255)], 2);
                atomicAdd(&sh[7 * 768 + 1 * 256 + min((int)(e1 * 2.0f), 255)], 2);
                atomicAdd(&sh[7 * 768 + 2 * 256 + min((int)(e2 * 2.0f), 255)], 2);
            }
        }
    }
    __syncthreads();
    int* gh = g_hist + b * 6144;
    for (int j = tid; j < 6144; j += 512)
        if (sh[j]) atomicAdd(&gh[j], sh[j]);
}
// sh layout: ((match*2 + side)*3 + c)*256 + bin == (match*2+side)*768 + c*256 + bin

// cumsum -> cdf -> searchsorted(left) -> float table
__global__ void k_table() {
    int b = blockIdx.y;
    int match = blockIdx.x / 3, c = blockIdx.x % 3;
    int i = threadIdx.x;
    const int* hb = g_hist + b * 6144;
    __shared__ int scS[256], scR[256];
    scS[i] = hb[(match * 2 + 0) * 768 + c * 256 + i];
    scR[i] = hb[(match * 2 + 1) * 768 + c * 256 + i];
    __syncthreads();
    for (int off = 1; off < 256; off <<= 1) {
        int vs = (i >= off) ? scS[i - off] : 0;
        int vr = (i >= off) ? scR[i - off] : 0;
        __syncthreads();
        scS[i] += vs; scR[i] += vr;
        __syncthreads();
    }
    float cs = (float)scS[i] / fmaxf((float)scS[255], 1e-6f);
    __shared__ float cdfR[256];
    cdfR[i] = (float)scR[i] / fmaxf((float)scR[255], 1e-6f);
    __syncthreads();
    int lo = 0, hi = 256;
    while (lo < hi) {
        int mid = (lo + hi) >> 1;
        if (cdfR[mid] < cs) lo = mid + 1; else hi = mid;
    }
    float t = (float)min(lo, 255);
    g_tabf[((b * 4 + match) * 3 + c) * 256 + i] = (t / 255.0f) * 2.0f - 1.0f;
}

// Final fused compose (float4 vectorized)
__global__ void k_compose(const float* __restrict__ src, const float* __restrict__ tgt,
                          const float* __restrict__ ms, float* __restrict__ out) {
    const int b = blockIdx.z;
    const int x0 = blockIdx.x * 128, y0 = blockIdx.y * 16;
    __shared__ float stab[3072];
    __shared__ unsigned char smse[20 * 132];
    const int tid = threadIdx.x;
    for (int j = tid; j < 3072; j += 256) stab[j] = g_tabf[b * 3072 + j];
    for (int j = tid; j < 20 * 132; j += 256) {
        int ry = j / 132, cx = j % 132;
        int y = y0 - 2 + ry, x = x0 - 2 + cx;
        unsigned char v = 0;
        if (y >= 0 && y < HH && x >= 0 && x < WW) v = g_mse8[b * HW + y * WW + x];
        smse[j] = v;
    }
    __syncthreads();
    const float4* is = (const float4*)(src + (size_t)b * 3 * HW);
    const float4* ir = (const float4*)(tgt + (size_t)b * 3 * HW);
    const float4* mk = (const float4*)(ms  + (size_t)b * 5 * HW);
    float4* ob = (float4*)(out + (size_t)b * 3 * HW);
    const int Q = HW / 4;

    for (int k = tid; k < 512; k += 256) {
        int row = k >> 5, col4 = (k & 31) << 2;
        int i4 = ((y0 + row) * WW + x0 + col4) >> 2;
        float4 m1f = mk[Q + i4], m4f = mk[4 * Q + i4], m0f = mk[i4];
        float4 a0 = is[i4], a1 = is[Q + i4], a2 = is[2 * Q + i4];
        float4 r0 = ir[i4], r1 = ir[Q + i4], r2 = ir[2 * Q + i4];
        float4 o0, o1, o2;
        float* po0 = &o0.x; float* po1 = &o1.x; float* po2 = &o2.x;
#pragma unroll
        for (int p = 0; p < 4; p++) {
            int col = col4 + p;
            float m1 = fcomp(m1f, p), m4 = fcomp(m4f, p), m0 = fcomp(m0f, p);
            int msei = smse[(row + 2) * 132 + col + 2];
            float mse = (float)msei;
            float mb = 0.0f;
            if (msei > 0) {
                int s = 0;
#pragma unroll
                for (int dy = 0; dy < 5; dy++)
#pragma unroll
                    for (int dx = 0; dx < 5; dx++)
                        s += smse[(row + dy) * 132 + col + dx];
                mb = ((float)s / 25.0f) * mse;
            }
            float av[3] = { fcomp(a0, p), fcomp(a1, p), fcomp(a2, p) };
            float rv[3] = { fcomp(r0, p), fcomp(r1, p), fcomp(r2, p) };
            float pv[3];
#pragma unroll
            for (int c = 0; c < 3; c++) {
                float a = av[c];
                float d = denorm255(a);
                int bi = (int)d;     // exact bin for binary masks
                float pgt = a;
                if (m1 > 0.0f) {
                    float xm = stab[(0 * 3 + c) * 256 + bi];
                    pgt = (1.0f - m1) * pgt + m1 * xm;
                }
                if (m4 > 0.0f) {
                    float xm = stab[(1 * 3 + c) * 256 + bi];
                    pgt = (1.0f - m4) * pgt + m4 * xm;
                }
                if (m0 > 0.0f) {
                    float xm = stab[(2 * 3 + c) * 256 + bi];
                    pgt = (1.0f - m0) * pgt + m0 * xm;
                }
                if (msei > 0) {
                    int be = min((int)(d * mse), 255);
                    float xm = stab[(3 * 3 + c) * 256 + be];
                    pgt = (1.0f - mb) * pgt + mb * xm;
                }
                float rch = rv[c];
                pgt = (1.0f - 0.3f * m1)  * pgt + 0.3f * m1  * rch;
                pgt = (1.0f - 0.8f * mse) * pgt + 0.8f * mse * rch;
                pgt = (1.0f - 0.1f * m0)  * pgt + 0.1f * m0  * rch;
                pv[c] = pgt;
            }
            po0[p] = pv[0]; po1[p] = pv[1]; po2[p] = pv[2];
        }
        ob[i4] = o0; ob[Q + i4] = o1; ob[2 * Q + i4] = o2;
    }
}

extern "C" void kernel_launch(void* const* d_in, const int* in_sizes, int n_in,
                              void* d_out, int out_size) {
    const float* src = (const float*)d_in[0];
    const float* tgt = (const float*)d_in[1];
    const float* ms  = (const float*)d_in[2];
    const float* mr  = (const float*)d_in[3];
    float* out = (float*)d_out;

    k_zero<<<96, 1024>>>();
    k_rowmax<<<dim3(1, 512, 32), 128>>>(ms, mr);
    k_colmax<<<dim3(16, 64, 32), dim3(32, 8)>>>(ms, mr);
    k_hist<<<dim3(32, 16), 512>>>(src, tgt, ms, mr);
    k_table<<<dim3(12, 16), 256>>>();
    k_compose<<<dim3(4, 32, 16), 256>>>(src, tgt, ms, out);
}

// round 3
// speedup vs baseline: 2.0342x; 1.3520x over previous
#include <cuda_runtime.h>

#define HH 512
#define WW 512
#define HW (512*512)
#define NB 16

// Scratch (static device memory)
__device__ unsigned char g_code[32 * HW];   // bit0=m0, bit1=m1, bit2=m4 (plane=side*16+b)
__device__ unsigned char g_tmp8[32 * HW];   // horizontal 25-max of (m2+m3), 0..2
__device__ unsigned char g_mse8[NB * HW];   // expanded eye mask (source), 0..2
__device__ unsigned char g_mre8[NB * HW];   // expanded eye mask (ref), 0..2
__device__ int   g_hist[NB * 24 * 256];     // [(match*2+side)*3 + c]*256 + bin
__device__ float g_tabf[NB * 12 * 256];     // pre-converted to renorm space

__device__ __forceinline__ float denorm255(float x) {
    return fminf(fmaxf((x + 1.0f) * 0.5f, 0.0f), 1.0f) * 255.0f;
}
__device__ __forceinline__ float fcomp(const float4& v, int p) {
    return p == 0 ? v.x : (p == 1 ? v.y : (p == 2 ? v.z : v.w));
}

__global__ void k_zero() {
    int i = blockIdx.x * 1024 + threadIdx.x;
    if (i < NB * 24 * 256) g_hist[i] = 0;
}

// Reads all 5 mask planes once: emits code byte + horizontal 25-max of (m2+m3)
__global__ void k_prep(const float* __restrict__ ms, const float* __restrict__ mr) {
    int plane = blockIdx.y;
    int b = plane & 15;
    const float* base = ((plane < 16) ? ms : mr) + (size_t)b * 5 * HW;
    int y = blockIdx.x;
    int t = threadIdx.x;  // 0..127
    const float4* p0 = (const float4*)(base + 0 * HW + y * WW);
    const float4* p1 = (const float4*)(base + 1 * HW + y * WW);
    const float4* p2 = (const float4*)(base + 2 * HW + y * WW);
    const float4* p3 = (const float4*)(base + 3 * HW + y * WW);
    const float4* p4 = (const float4*)(base + 4 * HW + y * WW);
    float4 v0 = p0[t], v1 = p1[t], v2 = p2[t], v3 = p3[t], v4 = p4[t];
    uchar4 code;
    code.x = (v0.x > 0.f) | ((v1.x > 0.f) << 1) | ((v4.x > 0.f) << 2);
    code.y = (v0.y > 0.f) | ((v1.y > 0.f) << 1) | ((v4.y > 0.f) << 2);
    code.z = (v0.z > 0.f) | ((v1.z > 0.f) << 1) | ((v4.z > 0.f) << 2);
    code.w = (v0.w > 0.f) | ((v1.w > 0.f) << 1) | ((v4.w > 0.f) << 2);
    *(uchar4*)(g_code + (size_t)plane * HW + y * WW + t * 4) = code;

    __shared__ float srow[536];
    *(float4*)&srow[12 + t * 4] =
        make_float4(v2.x + v3.x, v2.y + v3.y, v2.z + v3.z, v2.w + v3.w);
    if (t < 12) { srow[t] = 0.0f; srow[524 + t] = 0.0f; }
    __syncthreads();
    uchar4 o;
    unsigned char* po = &o.x;
    int x0 = t * 4;
#pragma unroll
    for (int k = 0; k < 4; k++) {
        float mx = 0.0f;
#pragma unroll
        for (int j = 0; j < 25; j++) mx = fmaxf(mx, srow[x0 + k + j]);
        po[k] = (unsigned char)mx;
    }
    *(uchar4*)(g_tmp8 + (size_t)plane * HW + y * WW + x0) = o;
}

// Vertical 25-tall max of g_tmp8, gated by m1 bit in code -> g_mse8 / g_mre8
__global__ void k_colmax() {
    int plane = blockIdx.z;
    int b = plane & 15;
    int x0 = blockIdx.x * 32, y0 = blockIdx.y * 32;
    __shared__ unsigned char t[56][32];
    int tid = threadIdx.x;  // 256 threads
    for (int j = tid; j < 448; j += 256) {
        int ry = j >> 3, cx = (j & 7) * 4;
        int y = y0 - 12 + ry;
        uchar4 v = make_uchar4(0, 0, 0, 0);
        if (y >= 0 && y < HH)
            v = *(const uchar4*)(g_tmp8 + (size_t)plane * HW + y * WW + x0 + cx);
        *(uchar4*)&t[ry][cx] = v;
    }
    __syncthreads();
    int tx = tid & 31, ty0 = tid >> 5;
    unsigned char* dst = ((plane < 16) ? g_mse8 : g_mre8) + (size_t)b * HW;
    const unsigned char* cd = g_code + (size_t)plane * HW;
#pragma unroll
    for (int r = 0; r < 4; r++) {
        int oy = ty0 + r * 8;
        int mx = 0;
#pragma unroll
        for (int j = 0; j < 25; j++) mx = max(mx, (int)t[oy + j][tx]);
        int pix = (y0 + oy) * WW + x0 + tx;
        dst[pix] = (cd[pix] & 2) ? (unsigned char)mx : 0;
    }
}

// Code-combined histograms: ONE atomic per (pixel,channel) for all 3 binary masks.
__global__ void k_hist(const float* __restrict__ src, const float* __restrict__ tgt) {
    __shared__ int shc[6144];  // [code(8)][ch(3)][bin(256)]
    __shared__ int she[768];   // eye: [ch(3)][bin(256)]
    int tid = threadIdx.x;
    for (int j = tid; j < 6144; j += 512) shc[j] = 0;
    for (int j = tid; j < 768; j += 512) she[j] = 0;
    __syncthreads();
    int side = blockIdx.z;
    int b = blockIdx.y;
    const float4* img = (const float4*)((side ? tgt : src) + (size_t)b * 3 * HW);
    const uchar4* cd  = (const uchar4*)(g_code + (size_t)((side << 4) | b) * HW);
    const uchar4* ey  = (const uchar4*)((side ? g_mre8 : g_mse8) + (size_t)b * HW);
    const int Q = HW / 4;

    for (int i = blockIdx.x * 512 + tid; i < Q; i += 8 * 512) {
        float4 v0 = img[i], v1 = img[Q + i], v2 = img[2 * Q + i];
        uchar4 c4 = cd[i], e4 = ey[i];
        unsigned char cv[4] = { c4.x, c4.y, c4.z, c4.w };
        unsigned char ev[4] = { e4.x, e4.y, e4.z, e4.w };
#pragma unroll
        for (int p = 0; p < 4; p++) {
            float d0 = denorm255(fcomp(v0, p));
            float d1 = denorm255(fcomp(v1, p));
            float d2 = denorm255(fcomp(v2, p));
            int code = cv[p];
            if (code) {
                int base = code * 768;
                atomicAdd(&shc[base + (int)d0], 1);
                atomicAdd(&shc[base + 256 + (int)d1], 1);
                atomicAdd(&shc[base + 512 + (int)d2], 1);
            }
            int w = ev[p];
            if (w) {
                float fw = (float)w;
                atomicAdd(&she[      min((int)(d0 * fw), 255)], w);
                atomicAdd(&she[256 + min((int)(d1 * fw), 255)], w);
                atomicAdd(&she[512 + min((int)(d2 * fw), 255)], w);
            }
        }
    }
    __syncthreads();
    // Convert code-hists to per-match and flush to global.
    // match0 = m1 (bit1): codes {2,3,6,7}; match1 = m4 (bit2): {4,5,6,7};
    // match2 = m0 (bit0): {1,3,5,7}; match3 = eye.
    int* gh = g_hist + b * 6144;
    for (int j = tid; j < 3072; j += 512) {
        int match = j / 768, r = j - match * 768;
        int v;
        if (match == 0)      v = shc[2*768+r] + shc[3*768+r] + shc[6*768+r] + shc[7*768+r];
        else if (match == 1) v = shc[4*768+r] + shc[5*768+r] + shc[6*768+r] + shc[7*768+r];
        else if (match == 2) v = shc[1*768+r] + shc[3*768+r] + shc[5*768+r] + shc[7*768+r];
        else                 v = she[r];
        if (v) atomicAdd(&gh[(match * 2 + side) * 768 + r], v);
    }
}

// cumsum -> cdf -> searchsorted(left) -> float table
__global__ void k_table() {
    int b = blockIdx.y;
    int match = blockIdx.x / 3, c = blockIdx.x % 3;
    int i = threadIdx.x;
    const int* hb = g_hist + b * 6144;
    __shared__ int scS[256], scR[256];
    scS[i] = hb[(match * 2 + 0) * 768 + c * 256 + i];
    scR[i] = hb[(match * 2 + 1) * 768 + c * 256 + i];
    __syncthreads();
    for (int off = 1; off < 256; off <<= 1) {
        int vs = (i >= off) ? scS[i - off] : 0;
        int vr = (i >= off) ? scR[i - off] : 0;
        __syncthreads();
        scS[i] += vs; scR[i] += vr;
        __syncthreads();
    }
    float cs = (float)scS[i] / fmaxf((float)scS[255], 1e-6f);
    __shared__ float cdfR[256];
    cdfR[i] = (float)scR[i] / fmaxf((float)scR[255], 1e-6f);
    __syncthreads();
    int lo = 0, hi = 256;
    while (lo < hi) {
        int mid = (lo + hi) >> 1;
        if (cdfR[mid] < cs) lo = mid + 1; else hi = mid;
    }
    float t = (float)min(lo, 255);
    g_tabf[((b * 4 + match) * 3 + c) * 256 + i] = (t / 255.0f) * 2.0f - 1.0f;
}

// Final fused compose (float4 vectorized, byte codes instead of float masks)
__global__ void k_compose(const float* __restrict__ src, const float* __restrict__ tgt,
                          float* __restrict__ out) {
    const int b = blockIdx.z;
    const int x0 = blockIdx.x * 128, y0 = blockIdx.y * 16;
    __shared__ float stab[3072];
    __shared__ unsigned char smse[20 * 132];
    const int tid = threadIdx.x;
    for (int j = tid; j < 3072; j += 256) stab[j] = g_tabf[b * 3072 + j];
    for (int j = tid; j < 20 * 132; j += 256) {
        int ry = j / 132, cx = j % 132;
        int y = y0 - 2 + ry, x = x0 - 2 + cx;
        unsigned char v = 0;
        if (y >= 0 && y < HH && x >= 0 && x < WW) v = g_mse8[(size_t)b * HW + y * WW + x];
        smse[j] = v;
    }
    __syncthreads();
    const float4* is = (const float4*)(src + (size_t)b * 3 * HW);
    const float4* ir = (const float4*)(tgt + (size_t)b * 3 * HW);
    const uchar4* cd = (const uchar4*)(g_code + (size_t)b * HW);
    float4* ob = (float4*)(out + (size_t)b * 3 * HW);
    const int Q = HW / 4;

    for (int k = tid; k < 512; k += 256) {
        int row = k >> 5, col4 = (k & 31) << 2;
        int i4 = ((y0 + row) * WW + x0 + col4) >> 2;
        uchar4 c4 = cd[i4];
        unsigned char cv[4] = { c4.x, c4.y, c4.z, c4.w };
        float4 a0 = is[i4], a1 = is[Q + i4], a2 = is[2 * Q + i4];
        float4 r0 = ir[i4], r1 = ir[Q + i4], r2 = ir[2 * Q + i4];
        float4 o0, o1, o2;
        float* po0 = &o0.x; float* po1 = &o1.x; float* po2 = &o2.x;
#pragma unroll
        for (int p = 0; p < 4; p++) {
            int col = col4 + p;
            int code = cv[p];
            float m0 = (code & 1) ? 1.0f : 0.0f;
            float m1 = (code & 2) ? 1.0f : 0.0f;
            float m4 = (code & 4) ? 1.0f : 0.0f;
            int msei = smse[(row + 2) * 132 + col + 2];
            float mse = (float)msei;
            float mb = 0.0f;
            if (msei > 0) {
                int s = 0;
#pragma unroll
                for (int dy = 0; dy < 5; dy++)
#pragma unroll
                    for (int dx = 0; dx < 5; dx++)
                        s += smse[(row + dy) * 132 + col + dx];
                mb = ((float)s / 25.0f) * mse;
            }
            float av[3] = { fcomp(a0, p), fcomp(a1, p), fcomp(a2, p) };
            float rv[3] = { fcomp(r0, p), fcomp(r1, p), fcomp(r2, p) };
            float pv[3];
#pragma unroll
            for (int c = 0; c < 3; c++) {
                float a = av[c];
                float d = denorm255(a);
                int bi = (int)d;
                float pgt = a;
                if (code & 2) pgt = stab[(0 * 3 + c) * 256 + bi];  // m1=1 exact
                if (code & 4) pgt = stab[(1 * 3 + c) * 256 + bi];  // m4=1
                if (code & 1) pgt = stab[(2 * 3 + c) * 256 + bi];  // m0=1
                if (msei > 0) {
                    int be = min((int)(d * mse), 255);
                    float xm = stab[(3 * 3 + c) * 256 + be];
                    pgt = (1.0f - mb) * pgt + mb * xm;
                }
                float rch = rv[c];
                pgt = (1.0f - 0.3f * m1)  * pgt + 0.3f * m1  * rch;
                pgt = (1.0f - 0.8f * mse) * pgt + 0.8f * mse * rch;
                pgt = (1.0f - 0.1f * m0)  * pgt + 0.1f * m0  * rch;
                pv[c] = pgt;
            }
            po0[p] = pv[0]; po1[p] = pv[1]; po2[p] = pv[2];
        }
        ob[i4] = o0; ob[Q + i4] = o1; ob[2 * Q + i4] = o2;
    }
}

extern "C" void kernel_launch(void* const* d_in, const int* in_sizes, int n_in,
                              void* d_out, int out_size) {
    const float* src = (const float*)d_in[0];
    const float* tgt = (const float*)d_in[1];
    const float* ms  = (const float*)d_in[2];
    const float* mr  = (const float*)d_in[3];
    float* out = (float*)d_out;

    k_zero<<<96, 1024>>>();
    k_prep<<<dim3(512, 32), 128>>>(ms, mr);
    k_colmax<<<dim3(16, 16, 32), 256>>>();
    k_hist<<<dim3(8, 16, 2), 512>>>(src, tgt);
    k_table<<<dim3(12, 16), 256>>>();
    k_compose<<<dim3(4, 32, 16), 256>>>(src, tgt, out);
}

// round 4
// speedup vs baseline: 2.0626x; 1.0140x over previous
#include <cuda_runtime.h>

#define HH 512
#define WW 512
#define HW (512*512)
#define NB 16

// Scratch (static device memory)
__device__ unsigned char g_code[32 * HW];   // bit0=m0, bit1=m1, bit2=m4 (plane=side*16+b)
__device__ unsigned char g_tmp8[32 * HW];   // horizontal 25-max of (m2+m3), 0..2
__device__ unsigned char g_mse8[NB * HW];   // expanded eye mask (source), 0..2
__device__ unsigned char g_mre8[NB * HW];   // expanded eye mask (ref), 0..2
__device__ int   g_hist[NB * 24 * 256];     // [(match*2+side)*3 + c]*256 + bin
__device__ float g_tabf[NB * 12 * 256];     // pre-converted to renorm space

__device__ __forceinline__ float denorm255(float x) {
    return fminf(fmaxf((x + 1.0f) * 0.5f, 0.0f), 1.0f) * 255.0f;
}
__device__ __forceinline__ float fcomp(const float4& v, int p) {
    return p == 0 ? v.x : (p == 1 ? v.y : (p == 2 ? v.z : v.w));
}

// Reads all 5 mask planes once: emits code byte + horizontal 25-max of (m2+m3).
// Also zeroes g_hist (folded k_zero).
__global__ void k_prep(const float* __restrict__ ms, const float* __restrict__ mr) {
    int t = threadIdx.x;  // 0..127
    if (blockIdx.y == 0 && blockIdx.x < 192) {
        ((int4*)g_hist)[blockIdx.x * 128 + t] = make_int4(0, 0, 0, 0);
    }
    int plane = blockIdx.y;
    int b = plane & 15;
    const float* base = ((plane < 16) ? ms : mr) + (size_t)b * 5 * HW;
    int y = blockIdx.x;
    const float4* p0 = (const float4*)(base + 0 * HW + y * WW);
    const float4* p1 = (const float4*)(base + 1 * HW + y * WW);
    const float4* p2 = (const float4*)(base + 2 * HW + y * WW);
    const float4* p3 = (const float4*)(base + 3 * HW + y * WW);
    const float4* p4 = (const float4*)(base + 4 * HW + y * WW);
    float4 v0 = p0[t], v1 = p1[t], v2 = p2[t], v3 = p3[t], v4 = p4[t];
    uchar4 code;
    code.x = (v0.x > 0.f) | ((v1.x > 0.f) << 1) | ((v4.x > 0.f) << 2);
    code.y = (v0.y > 0.f) | ((v1.y > 0.f) << 1) | ((v4.y > 0.f) << 2);
    code.z = (v0.z > 0.f) | ((v1.z > 0.f) << 1) | ((v4.z > 0.f) << 2);
    code.w = (v0.w > 0.f) | ((v1.w > 0.f) << 1) | ((v4.w > 0.f) << 2);
    *(uchar4*)(g_code + (size_t)plane * HW + y * WW + t * 4) = code;

    __shared__ float srow[536];
    *(float4*)&srow[12 + t * 4] =
        make_float4(v2.x + v3.x, v2.y + v3.y, v2.z + v3.z, v2.w + v3.w);
    if (t < 12) { srow[t] = 0.0f; srow[524 + t] = 0.0f; }
    __syncthreads();
    int x0 = t * 4;
    // out[x] = max(srow[x .. x+24]); common interior = srow[x0+3 .. x0+24]
    float common = srow[x0 + 3];
#pragma unroll
    for (int j = 4; j <= 24; j++) common = fmaxf(common, srow[x0 + j]);
    uchar4 o;
    o.x = (unsigned char)fmaxf(fmaxf(srow[x0], srow[x0 + 1]), fmaxf(srow[x0 + 2], common));
    o.y = (unsigned char)fmaxf(fmaxf(srow[x0 + 1], srow[x0 + 2]), fmaxf(common, srow[x0 + 25]));
    o.z = (unsigned char)fmaxf(fmaxf(srow[x0 + 2], common), fmaxf(srow[x0 + 25], srow[x0 + 26]));
    o.w = (unsigned char)fmaxf(fmaxf(common, srow[x0 + 25]), fmaxf(srow[x0 + 26], srow[x0 + 27]));
    *(uchar4*)(g_tmp8 + (size_t)plane * HW + y * WW + x0) = o;
}

// Vertical 25-tall max of g_tmp8, gated by m1 bit in code -> g_mse8 / g_mre8
__global__ void k_colmax() {
    int plane = blockIdx.z;
    int b = plane & 15;
    int x0 = blockIdx.x * 32, y0 = blockIdx.y * 32;
    __shared__ unsigned char t[56][32];
    int tid = threadIdx.x;  // 256 threads
    for (int j = tid; j < 448; j += 256) {
        int ry = j >> 3, cx = (j & 7) * 4;
        int y = y0 - 12 + ry;
        uchar4 v = make_uchar4(0, 0, 0, 0);
        if (y >= 0 && y < HH)
            v = *(const uchar4*)(g_tmp8 + (size_t)plane * HW + y * WW + x0 + cx);
        *(uchar4*)&t[ry][cx] = v;
    }
    __syncthreads();
    int tx = tid & 31;
    int oy = (tid >> 5) * 4;   // 4 consecutive output rows per thread
    // window rows [oy+r, oy+r+25); common interior rows [oy+3, oy+24]
    int common = t[oy + 3][tx];
#pragma unroll
    for (int j = 4; j <= 24; j++) common = max(common, (int)t[oy + j][tx]);
    int o0 = max(max((int)t[oy][tx], (int)t[oy + 1][tx]), max((int)t[oy + 2][tx], common));
    int o1 = max(max((int)t[oy + 1][tx], (int)t[oy + 2][tx]), max(common, (int)t[oy + 25][tx]));
    int o2 = max(max((int)t[oy + 2][tx], common), max((int)t[oy + 25][tx], (int)t[oy + 26][tx]));
    int o3 = max(max(common, (int)t[oy + 25][tx]), max((int)t[oy + 26][tx], (int)t[oy + 27][tx]));
    unsigned char* dst = ((plane < 16) ? g_mse8 : g_mre8) + (size_t)b * HW;
    const unsigned char* cd = g_code + (size_t)plane * HW;
    int ov[4] = { o0, o1, o2, o3 };
#pragma unroll
    for (int r = 0; r < 4; r++) {
        int pix = (y0 + oy + r) * WW + x0 + tx;
        dst[pix] = (cd[pix] & 2) ? (unsigned char)ov[r] : 0;
    }
}

// Code-combined histograms: ONE atomic per (pixel,channel) for all 3 binary masks.
__global__ void k_hist(const float* __restrict__ src, const float* __restrict__ tgt) {
    __shared__ int shc[6144];  // [code(8)][ch(3)][bin(256)]
    __shared__ int she[768];   // eye: [ch(3)][bin(256)]
    int tid = threadIdx.x;
    for (int j = tid; j < 6144; j += 512) shc[j] = 0;
    for (int j = tid; j < 768; j += 512) she[j] = 0;
    __syncthreads();
    int side = blockIdx.z;
    int b = blockIdx.y;
    const float4* img = (const float4*)((side ? tgt : src) + (size_t)b * 3 * HW);
    const uchar4* cd  = (const uchar4*)(g_code + (size_t)((side << 4) | b) * HW);
    const uchar4* ey  = (const uchar4*)((side ? g_mre8 : g_mse8) + (size_t)b * HW);
    const int Q = HW / 4;

    for (int i = blockIdx.x * 512 + tid; i < Q; i += 14 * 512) {
        float4 v0 = img[i], v1 = img[Q + i], v2 = img[2 * Q + i];
        uchar4 c4 = cd[i], e4 = ey[i];
        unsigned char cv[4] = { c4.x, c4.y, c4.z, c4.w };
        unsigned char ev[4] = { e4.x, e4.y, e4.z, e4.w };
#pragma unroll
        for (int p = 0; p < 4; p++) {
            float d0 = denorm255(fcomp(v0, p));
            float d1 = denorm255(fcomp(v1, p));
            float d2 = denorm255(fcomp(v2, p));
            int code = cv[p];
            if (code) {
                int base = code * 768;
                atomicAdd(&shc[base + (int)d0], 1);
                atomicAdd(&shc[base + 256 + (int)d1], 1);
                atomicAdd(&shc[base + 512 + (int)d2], 1);
            }
            int w = ev[p];
            if (w == 2) {
                atomicAdd(&she[      min((int)(d0 * 2.0f), 255)], 2);
                atomicAdd(&she[256 + min((int)(d1 * 2.0f), 255)], 2);
                atomicAdd(&she[512 + min((int)(d2 * 2.0f), 255)], 2);
            } else if (w == 1) {
                atomicAdd(&she[      (int)d0], 1);
                atomicAdd(&she[256 + (int)d1], 1);
                atomicAdd(&she[512 + (int)d2], 1);
            }
        }
    }
    __syncthreads();
    // match0 = m1 (bit1): codes {2,3,6,7}; match1 = m4 (bit2): {4,5,6,7};
    // match2 = m0 (bit0): {1,3,5,7}; match3 = eye.
    int* gh = g_hist + b * 6144;
    for (int j = tid; j < 3072; j += 512) {
        int match = j / 768, r = j - match * 768;
        int v;
        if (match == 0)      v = shc[2*768+r] + shc[3*768+r] + shc[6*768+r] + shc[7*768+r];
        else if (match == 1) v = shc[4*768+r] + shc[5*768+r] + shc[6*768+r] + shc[7*768+r];
        else if (match == 2) v = shc[1*768+r] + shc[3*768+r] + shc[5*768+r] + shc[7*768+r];
        else                 v = she[r];
        if (v) atomicAdd(&gh[(match * 2 + side) * 768 + r], v);
    }
}

// cumsum -> cdf -> searchsorted(left) -> float table
__global__ void k_table() {
    int b = blockIdx.y;
    int match = blockIdx.x / 3, c = blockIdx.x % 3;
    int i = threadIdx.x;
    const int* hb = g_hist + b * 6144;
    __shared__ int scS[256], scR[256];
    scS[i] = hb[(match * 2 + 0) * 768 + c * 256 + i];
    scR[i] = hb[(match * 2 + 1) * 768 + c * 256 + i];
    __syncthreads();
    for (int off = 1; off < 256; off <<= 1) {
        int vs = (i >= off) ? scS[i - off] : 0;
        int vr = (i >= off) ? scR[i - off] : 0;
        __syncthreads();
        scS[i] += vs; scR[i] += vr;
        __syncthreads();
    }
    float cs = (float)scS[i] / fmaxf((float)scS[255], 1e-6f);
    __shared__ float cdfR[256];
    cdfR[i] = (float)scR[i] / fmaxf((float)scR[255], 1e-6f);
    __syncthreads();
    int lo = 0, hi = 256;
    while (lo < hi) {
        int mid = (lo + hi) >> 1;
        if (cdfR[mid] < cs) lo = mid + 1; else hi = mid;
    }
    float t = (float)min(lo, 255);
    g_tabf[((b * 4 + match) * 3 + c) * 256 + i] = (t / 255.0f) * 2.0f - 1.0f;
}

// Final fused compose (float4 vectorized, byte codes, 128x32 tiles, 512 thr)
__global__ void k_compose(const float* __restrict__ src, const float* __restrict__ tgt,
                          float* __restrict__ out) {
    const int b = blockIdx.z;
    const int x0 = blockIdx.x * 128, y0 = blockIdx.y * 32;
    __shared__ float stab[3072];
    __shared__ unsigned char smse[36 * 132];
    const int tid = threadIdx.x;  // 512
    for (int j = tid; j < 3072; j += 512) stab[j] = g_tabf[b * 3072 + j];
    for (int j = tid; j < 36 * 132; j += 512) {
        int ry = j / 132, cx = j % 132;
        int y = y0 - 2 + ry, x = x0 - 2 + cx;
        unsigned char v = 0;
        if (y >= 0 && y < HH && x >= 0 && x < WW) v = g_mse8[(size_t)b * HW + y * WW + x];
        smse[j] = v;
    }
    __syncthreads();
    const float4* is = (const float4*)(src + (size_t)b * 3 * HW);
    const float4* ir = (const float4*)(tgt + (size_t)b * 3 * HW);
    const uchar4* cd = (const uchar4*)(g_code + (size_t)b * HW);
    float4* ob = (float4*)(out + (size_t)b * 3 * HW);
    const int Q = HW / 4;

    for (int k = tid; k < 1024; k += 512) {
        int row = k >> 5, col4 = (k & 31) << 2;
        int i4 = ((y0 + row) * WW + x0 + col4) >> 2;
        uchar4 c4 = cd[i4];
        unsigned char cv[4] = { c4.x, c4.y, c4.z, c4.w };
        float4 a0 = is[i4], a1 = is[Q + i4], a2 = is[2 * Q + i4];
        float4 r0 = ir[i4], r1 = ir[Q + i4], r2 = ir[2 * Q + i4];
        float4 o0, o1, o2;
        float* po0 = &o0.x; float* po1 = &o1.x; float* po2 = &o2.x;
#pragma unroll
        for (int p = 0; p < 4; p++) {
            int col = col4 + p;
            int code = cv[p];
            float m0 = (code & 1) ? 1.0f : 0.0f;
            float m1 = (code & 2) ? 1.0f : 0.0f;
            int msei = smse[(row + 2) * 132 + col + 2];
            float mse = (float)msei;
            float mb = 0.0f;
            if (msei > 0) {
                int s = 0;
#pragma unroll
                for (int dy = 0; dy < 5; dy++)
#pragma unroll
                    for (int dx = 0; dx < 5; dx++)
                        s += smse[(row + dy) * 132 + col + dx];
                mb = ((float)s / 25.0f) * mse;
            }
            float av[3] = { fcomp(a0, p), fcomp(a1, p), fcomp(a2, p) };
            float rv[3] = { fcomp(r0, p), fcomp(r1, p), fcomp(r2, p) };
            float pv[3];
#pragma unroll
            for (int c = 0; c < 3; c++) {
                float a = av[c];
                float d = denorm255(a);
                int bi = (int)d;
                float pgt = a;
                if (code & 2) pgt = stab[(0 * 3 + c) * 256 + bi];  // m1=1 exact
                if (code & 4) pgt = stab[(1 * 3 + c) * 256 + bi];  // m4=1
                if (code & 1) pgt = stab[(2 * 3 + c) * 256 + bi];  // m0=1
                if (msei > 0) {
                    int be = min((int)(d * mse), 255);
                    float xm = stab[(3 * 3 + c) * 256 + be];
                    pgt = (1.0f - mb) * pgt + mb * xm;
                }
                float rch = rv[c];
                pgt = (1.0f - 0.3f * m1)  * pgt + 0.3f * m1  * rch;
                pgt = (1.0f - 0.8f * mse) * pgt + 0.8f * mse * rch;
                pgt = (1.0f - 0.1f * m0)  * pgt + 0.1f * m0  * rch;
                pv[c] = pgt;
            }
            po0[p] = pv[0]; po1[p] = pv[1]; po2[p] = pv[2];
        }
        ob[i4] = o0; ob[Q + i4] = o1; ob[2 * Q + i4] = o2;
    }
}

extern "C" void kernel_launch(void* const* d_in, const int* in_sizes, int n_in,
                              void* d_out, int out_size) {
    const float* src = (const float*)d_in[0];
    const float* tgt = (const float*)d_in[1];
    const float* ms  = (const float*)d_in[2];
    const float* mr  = (const float*)d_in[3];
    float* out = (float*)d_out;

    k_prep<<<dim3(512, 32), 128>>>(ms, mr);
    k_colmax<<<dim3(16, 16, 32), 256>>>();
    k_hist<<<dim3(14, 16, 2), 512>>>(src, tgt);
    k_table<<<dim3(12, 16), 256>>>();
    k_compose<<<dim3(4, 16, 16), 512>>>(src, tgt, out);
}